// round 5
// baseline (speedup 1.0000x reference)
#include <cuda_runtime.h>

#define BATCH  16384
#define H      256
#define S      8
#define THREADS 256
#define NBLK   (BATCH / S)
// two ping-pong activation buffers: [S][H][8] floats each
#define SMEM_BYTES (2 * S * H * 8 * 4)

// ---------- packed f32x2 helpers (Blackwell FFMA2 path) ----------
__device__ __forceinline__ unsigned long long pack2(float lo, float hi) {
    unsigned long long r;
    asm("mov.b64 %0, {%1, %2};" : "=l"(r) : "f"(lo), "f"(hi));
    return r;
}
__device__ __forceinline__ void unpack2(unsigned long long v, float& lo, float& hi) {
    asm("mov.b64 {%0, %1}, %2;" : "=f"(lo), "=f"(hi) : "l"(v));
}
__device__ __forceinline__ unsigned long long ffma2(unsigned long long a,
                                                    unsigned long long b,
                                                    unsigned long long c) {
    unsigned long long d;
    asm("fma.rn.f32x2 %0, %1, %2, %3;" : "=l"(d) : "l"(a), "l"(b), "l"(c));
    return d;
}

// One hidden layer: pre-acts for 8 streams x S samples, then coupled tanh epilogue.
// sin/sout: [S][H][8] float in shared. Thread j owns output neuron j.
__device__ __forceinline__ void hidden_layer(const float* __restrict__ W,
                                             const float* __restrict__ b,
                                             const float* sin, float* sout, int j) {
    unsigned long long acc[S][4];
    const float bj = b[j];
#pragma unroll
    for (int s = 0; s < S; s++) {
        acc[s][0] = pack2(bj, 0.f);   // bias into stream 0
        acc[s][1] = pack2(0.f, 0.f);
        acc[s][2] = pack2(0.f, 0.f);
        acc[s][3] = pack2(0.f, 0.f);
    }

#pragma unroll 2
    for (int k0 = 0; k0 < H; k0 += 4) {
        const float w0 = W[(k0 + 0) * H + j];
        const float w1 = W[(k0 + 1) * H + j];
        const float w2 = W[(k0 + 2) * H + j];
        const float w3 = W[(k0 + 3) * H + j];
        const unsigned long long wp0 = pack2(w0, w0);
        const unsigned long long wp1 = pack2(w1, w1);
        const unsigned long long wp2 = pack2(w2, w2);
        const unsigned long long wp3 = pack2(w3, w3);
#pragma unroll
        for (int s = 0; s < S; s++) {
            const ulonglong2* hp = (const ulonglong2*)(sin + (s * H + k0) * 8);
            ulonglong2 qa = hp[0], qb = hp[1];   // k0+0: streams 0-3, 4-7
            acc[s][0] = ffma2(qa.x, wp0, acc[s][0]);
            acc[s][1] = ffma2(qa.y, wp0, acc[s][1]);
            acc[s][2] = ffma2(qb.x, wp0, acc[s][2]);
            acc[s][3] = ffma2(qb.y, wp0, acc[s][3]);
            ulonglong2 qc = hp[2], qd = hp[3];   // k0+1
            acc[s][0] = ffma2(qc.x, wp1, acc[s][0]);
            acc[s][1] = ffma2(qc.y, wp1, acc[s][1]);
            acc[s][2] = ffma2(qd.x, wp1, acc[s][2]);
            acc[s][3] = ffma2(qd.y, wp1, acc[s][3]);
            ulonglong2 qe = hp[4], qf = hp[5];   // k0+2
            acc[s][0] = ffma2(qe.x, wp2, acc[s][0]);
            acc[s][1] = ffma2(qe.y, wp2, acc[s][1]);
            acc[s][2] = ffma2(qf.x, wp2, acc[s][2]);
            acc[s][3] = ffma2(qf.y, wp2, acc[s][3]);
            ulonglong2 qg = hp[6], qh = hp[7];   // k0+3
            acc[s][0] = ffma2(qg.x, wp3, acc[s][0]);
            acc[s][1] = ffma2(qg.y, wp3, acc[s][1]);
            acc[s][2] = ffma2(qh.x, wp3, acc[s][2]);
            acc[s][3] = ffma2(qh.y, wp3, acc[s][3]);
        }
    }

    // coupled tanh epilogue: v, v'_i = t a'_i, v''_i = t(a''_i - 2 v a'_i^2)
#pragma unroll
    for (int s = 0; s < S; s++) {
        float a0, a1, a2, a3, a4, a5, a6, a7;
        unpack2(acc[s][0], a0, a1);
        unpack2(acc[s][1], a2, a3);
        unpack2(acc[s][2], a4, a5);
        unpack2(acc[s][3], a6, a7);
        const float v = tanhf(a0);
        const float t = fmaf(-v, v, 1.f);
        const float o1 = t * a1, o2 = t * a2, o3 = t * a3, o4 = t * a4;
        const float m = -2.f * v * t;
        const float o5 = fmaf(t, a5, m * a1 * a1);
        const float o6 = fmaf(t, a6, m * a2 * a2);
        const float o7 = fmaf(t, a7, m * a3 * a3);
        float4* op = (float4*)(sout + (s * H + j) * 8);
        op[0] = make_float4(v, o1, o2, o3);
        op[1] = make_float4(o4, o5, o6, o7);
    }
}

extern "C" __global__ void __launch_bounds__(THREADS, 1)
grad_mlp_kernel(const float* __restrict__ x,
                const float* __restrict__ W0, const float* __restrict__ b0,
                const float* __restrict__ W1, const float* __restrict__ b1,
                const float* __restrict__ W2, const float* __restrict__ b2,
                const float* __restrict__ W3, const float* __restrict__ b3,
                const float* __restrict__ Wo, const float* __restrict__ bo,
                float* __restrict__ out) {
    extern __shared__ float sh[];
    float* bufA = sh;
    float* bufB = sh + S * H * 8;
    __shared__ float xsh[S * 4];

    const int j  = threadIdx.x;
    const int s0 = blockIdx.x * S;

    if (j < S * 4) xsh[j] = x[s0 * 4 + j];
    __syncthreads();

    // ---- layer 0 (4 -> 256): tangents are W0 rows, second-order pre-act = 0
    {
        const float w0 = W0[0 * H + j], w1 = W0[1 * H + j];
        const float w2 = W0[2 * H + j], w3 = W0[3 * H + j];
        const float bj = b0[j];
#pragma unroll
        for (int s = 0; s < S; s++) {
            float a = bj;
            a = fmaf(xsh[s * 4 + 0], w0, a);
            a = fmaf(xsh[s * 4 + 1], w1, a);
            a = fmaf(xsh[s * 4 + 2], w2, a);
            a = fmaf(xsh[s * 4 + 3], w3, a);
            const float v = tanhf(a);
            const float t = fmaf(-v, v, 1.f);
            const float m = -2.f * v * t;
            float4* op = (float4*)(bufA + (s * H + j) * 8);
            op[0] = make_float4(v, t * w0, t * w1, t * w2);
            op[1] = make_float4(t * w3, m * w0 * w0, m * w1 * w1, m * w2 * w2);
        }
    }
    __syncthreads();

    hidden_layer(W1, b1, bufA, bufB, j);
    __syncthreads();
    hidden_layer(W2, b2, bufB, bufA, j);
    __syncthreads();
    hidden_layer(W3, b3, bufA, bufB, j);
    __syncthreads();

    // ---- output layer (256 -> 2) + derived quantities: warp w handles sample w
    const int warp = j >> 5, lane = j & 31;
    if (warp < S) {
        float r[8][2];
#pragma unroll
        for (int rr = 0; rr < 8; rr++) { r[rr][0] = 0.f; r[rr][1] = 0.f; }
        const float* hb = bufB + warp * H * 8;
#pragma unroll
        for (int it = 0; it < H / 32; it++) {
            const int k = lane + it * 32;
            const float2 wv = ((const float2*)Wo)[k];
            const float4* hp = (const float4*)(hb + k * 8);
            const float4 h0 = hp[0], h1 = hp[1];
            r[0][0] = fmaf(h0.x, wv.x, r[0][0]); r[0][1] = fmaf(h0.x, wv.y, r[0][1]);
            r[1][0] = fmaf(h0.y, wv.x, r[1][0]); r[1][1] = fmaf(h0.y, wv.y, r[1][1]);
            r[2][0] = fmaf(h0.z, wv.x, r[2][0]); r[2][1] = fmaf(h0.z, wv.y, r[2][1]);
            r[3][0] = fmaf(h0.w, wv.x, r[3][0]); r[3][1] = fmaf(h0.w, wv.y, r[3][1]);
            r[4][0] = fmaf(h1.x, wv.x, r[4][0]); r[4][1] = fmaf(h1.x, wv.y, r[4][1]);
            r[5][0] = fmaf(h1.y, wv.x, r[5][0]); r[5][1] = fmaf(h1.y, wv.y, r[5][1]);
            r[6][0] = fmaf(h1.z, wv.x, r[6][0]); r[6][1] = fmaf(h1.z, wv.y, r[6][1]);
            r[7][0] = fmaf(h1.w, wv.x, r[7][0]); r[7][1] = fmaf(h1.w, wv.y, r[7][1]);
        }
#pragma unroll
        for (int rr = 0; rr < 8; rr++) {
#pragma unroll
            for (int off = 16; off > 0; off >>= 1) {
                r[rr][0] += __shfl_xor_sync(0xffffffffu, r[rr][0], off);
                r[rr][1] += __shfl_xor_sync(0xffffffffu, r[rr][1], off);
            }
        }
        if (lane == 0) {
            const int gs = s0 + warp;
            const float c   = r[0][0] + bo[0];
            const float Fi  = r[0][1] + bo[1];
            const float cg0 = r[1][0], cg1 = r[2][0], cg2 = r[3][0];
            const float fg0 = r[1][1], fg1 = r[2][1], fg2 = r[3][1];
            const float c_t = r[4][0];                       // d/dx3 of c
            const float trHc = r[5][0] + r[6][0] + r[7][0];  // sum d2c/dxi2
            const float fila = r[5][1] + r[6][1] + r[7][1];  // Fi laplacian
            const float jdiv = -trHc
                               - (cg0 * fg0 + cg1 * fg1 + cg2 * fg2 + c * fila)
                               + 0.1f * (cg0 + cg1 + cg2);
            const int B = BATCH;
            out[gs]              = c;
            out[B + gs]          = c_t;
            out[2 * B + gs * 3 + 0] = cg0;
            out[2 * B + gs * 3 + 1] = cg1;
            out[2 * B + gs * 3 + 2] = cg2;
            out[5 * B + gs]      = Fi;
            out[6 * B + gs * 3 + 0] = fg0;
            out[6 * B + gs * 3 + 1] = fg1;
            out[6 * B + gs * 3 + 2] = fg2;
            out[9 * B + gs]      = fila;
            out[10 * B + gs]     = jdiv;
        }
    }
}

extern "C" void kernel_launch(void* const* d_in, const int* in_sizes, int n_in,
                              void* d_out, int out_size) {
    const float* x  = (const float*)d_in[0];
    const float* W0 = (const float*)d_in[1];
    const float* b0 = (const float*)d_in[2];
    const float* W1 = (const float*)d_in[3];
    const float* b1 = (const float*)d_in[4];
    const float* W2 = (const float*)d_in[5];
    const float* b2 = (const float*)d_in[6];
    const float* W3 = (const float*)d_in[7];
    const float* b3 = (const float*)d_in[8];
    const float* Wo = (const float*)d_in[9];
    const float* bo = (const float*)d_in[10];

    cudaFuncSetAttribute(grad_mlp_kernel,
                         cudaFuncAttributeMaxDynamicSharedMemorySize, SMEM_BYTES);
    grad_mlp_kernel<<<NBLK, THREADS, SMEM_BYTES>>>(
        x, W0, b0, W1, b1, W2, b2, W3, b3, Wo, bo, (float*)d_out);
}

// round 6
// speedup vs baseline: 1.2847x; 1.2847x over previous
#include <cuda_runtime.h>

#define BATCH  16384
#define H      256
#define S      8          // samples per CTA
#define SPT    2          // samples per thread
#define NPT    4          // neurons per thread
#define THREADS 256
#define NBLK   (BATCH / S)
// two ping-pong activation buffers: [S][H][8] floats each
#define SMEM_BYTES (2 * S * H * 8 * 4)

// ---------- packed f32x2 helpers (Blackwell FFMA2 path) ----------
__device__ __forceinline__ unsigned long long pack2(float lo, float hi) {
    unsigned long long r;
    asm("mov.b64 %0, {%1, %2};" : "=l"(r) : "f"(lo), "f"(hi));
    return r;
}
__device__ __forceinline__ void unpack2(unsigned long long v, float& lo, float& hi) {
    asm("mov.b64 {%0, %1}, %2;" : "=f"(lo), "=f"(hi) : "l"(v));
}
__device__ __forceinline__ unsigned long long ffma2(unsigned long long a,
                                                    unsigned long long b,
                                                    unsigned long long c) {
    unsigned long long d;
    asm("fma.rn.f32x2 %0, %1, %2, %3;" : "=l"(d) : "l"(a), "l"(b), "l"(c));
    return d;
}

// One hidden layer. Thread computes NPT neurons (j0 + 64n) for SPT samples
// (sbase + s). All lanes of a warp share (sbase) -> activation LDS broadcast.
// sin/sout: [S][H][8] float in shared.
__device__ __forceinline__ void hidden_layer(const float* __restrict__ W,
                                             const float* __restrict__ b,
                                             const float* sin, float* sout,
                                             int j0, int sbase) {
    unsigned long long acc[NPT][SPT][4];
#pragma unroll
    for (int n = 0; n < NPT; n++) {
        const float bj = b[j0 + 64 * n];
#pragma unroll
        for (int s = 0; s < SPT; s++) {
            acc[n][s][0] = pack2(bj, 0.f);   // bias into stream 0
            acc[n][s][1] = 0ULL;
            acc[n][s][2] = 0ULL;
            acc[n][s][3] = 0ULL;
        }
    }

#pragma unroll 2
    for (int k0 = 0; k0 < H; k0 += 4) {
        unsigned long long wp[4][NPT];
#pragma unroll
        for (int kk = 0; kk < 4; kk++) {
#pragma unroll
            for (int n = 0; n < NPT; n++) {
                const float w = W[(k0 + kk) * H + j0 + 64 * n];
                wp[kk][n] = pack2(w, w);
            }
        }
#pragma unroll
        for (int s = 0; s < SPT; s++) {
            const ulonglong2* hp =
                (const ulonglong2*)(sin + ((sbase + s) * H + k0) * 8);
            const ulonglong2 q0 = hp[0], q1 = hp[1];   // k0+0: streams 0-3,4-7
            const ulonglong2 q2 = hp[2], q3 = hp[3];   // k0+1
            const ulonglong2 q4 = hp[4], q5 = hp[5];   // k0+2
            const ulonglong2 q6 = hp[6], q7 = hp[7];   // k0+3
#pragma unroll
            for (int n = 0; n < NPT; n++) {
                acc[n][s][0] = ffma2(q0.x, wp[0][n], acc[n][s][0]);
                acc[n][s][1] = ffma2(q0.y, wp[0][n], acc[n][s][1]);
                acc[n][s][2] = ffma2(q1.x, wp[0][n], acc[n][s][2]);
                acc[n][s][3] = ffma2(q1.y, wp[0][n], acc[n][s][3]);
                acc[n][s][0] = ffma2(q2.x, wp[1][n], acc[n][s][0]);
                acc[n][s][1] = ffma2(q2.y, wp[1][n], acc[n][s][1]);
                acc[n][s][2] = ffma2(q3.x, wp[1][n], acc[n][s][2]);
                acc[n][s][3] = ffma2(q3.y, wp[1][n], acc[n][s][3]);
                acc[n][s][0] = ffma2(q4.x, wp[2][n], acc[n][s][0]);
                acc[n][s][1] = ffma2(q4.y, wp[2][n], acc[n][s][1]);
                acc[n][s][2] = ffma2(q5.x, wp[2][n], acc[n][s][2]);
                acc[n][s][3] = ffma2(q5.y, wp[2][n], acc[n][s][3]);
                acc[n][s][0] = ffma2(q6.x, wp[3][n], acc[n][s][0]);
                acc[n][s][1] = ffma2(q6.y, wp[3][n], acc[n][s][1]);
                acc[n][s][2] = ffma2(q7.x, wp[3][n], acc[n][s][2]);
                acc[n][s][3] = ffma2(q7.y, wp[3][n], acc[n][s][3]);
            }
        }
    }

    // coupled tanh epilogue: v, v'_i = t a'_i, v''_i = t(a''_i - 2 v a'_i^2)
#pragma unroll
    for (int n = 0; n < NPT; n++) {
#pragma unroll
        for (int s = 0; s < SPT; s++) {
            float a0, a1, a2, a3, a4, a5, a6, a7;
            unpack2(acc[n][s][0], a0, a1);
            unpack2(acc[n][s][1], a2, a3);
            unpack2(acc[n][s][2], a4, a5);
            unpack2(acc[n][s][3], a6, a7);
            const float v = tanhf(a0);
            const float t = fmaf(-v, v, 1.f);
            const float o1 = t * a1, o2 = t * a2, o3 = t * a3, o4 = t * a4;
            const float m = -2.f * v * t;
            const float o5 = fmaf(t, a5, m * a1 * a1);
            const float o6 = fmaf(t, a6, m * a2 * a2);
            const float o7 = fmaf(t, a7, m * a3 * a3);
            float4* op =
                (float4*)(sout + ((sbase + s) * H + j0 + 64 * n) * 8);
            op[0] = make_float4(v, o1, o2, o3);
            op[1] = make_float4(o4, o5, o6, o7);
        }
    }
}

extern "C" __global__ void __launch_bounds__(THREADS, 1)
grad_mlp_kernel(const float* __restrict__ x,
                const float* __restrict__ W0, const float* __restrict__ b0,
                const float* __restrict__ W1, const float* __restrict__ b1,
                const float* __restrict__ W2, const float* __restrict__ b2,
                const float* __restrict__ W3, const float* __restrict__ b3,
                const float* __restrict__ Wo, const float* __restrict__ bo,
                float* __restrict__ out) {
    extern __shared__ float sh[];
    float* bufA = sh;
    float* bufB = sh + S * H * 8;
    __shared__ float xsh[S * 4];

    const int tid  = threadIdx.x;
    const int warp = tid >> 5, lane = tid & 31;
    const int group = warp >> 1;                 // 0..3: sample group
    const int jt    = ((warp & 1) << 5) | lane;  // 0..63: base neuron
    const int sbase = group * SPT;
    const int s0    = blockIdx.x * S;

    if (tid < S * 4) xsh[tid] = x[s0 * 4 + tid];
    __syncthreads();

    // ---- layer 0 (4 -> 256): tangents are W0 rows, second-order pre-act = 0
#pragma unroll
    for (int n = 0; n < NPT; n++) {
        const int j = jt + 64 * n;
        const float w0 = W0[0 * H + j], w1 = W0[1 * H + j];
        const float w2 = W0[2 * H + j], w3 = W0[3 * H + j];
        const float bj = b0[j];
#pragma unroll
        for (int s = 0; s < SPT; s++) {
            const int gs = sbase + s;
            float a = bj;
            a = fmaf(xsh[gs * 4 + 0], w0, a);
            a = fmaf(xsh[gs * 4 + 1], w1, a);
            a = fmaf(xsh[gs * 4 + 2], w2, a);
            a = fmaf(xsh[gs * 4 + 3], w3, a);
            const float v = tanhf(a);
            const float t = fmaf(-v, v, 1.f);
            const float m = -2.f * v * t;
            float4* op = (float4*)(bufA + (gs * H + j) * 8);
            op[0] = make_float4(v, t * w0, t * w1, t * w2);
            op[1] = make_float4(t * w3, m * w0 * w0, m * w1 * w1, m * w2 * w2);
        }
    }
    __syncthreads();

    hidden_layer(W1, b1, bufA, bufB, jt, sbase);
    __syncthreads();
    hidden_layer(W2, b2, bufB, bufA, jt, sbase);
    __syncthreads();
    hidden_layer(W3, b3, bufA, bufB, jt, sbase);
    __syncthreads();

    // ---- output layer (256 -> 2) + derived quantities: warp w handles sample w
    if (warp < S) {
        float r[8][2];
#pragma unroll
        for (int rr = 0; rr < 8; rr++) { r[rr][0] = 0.f; r[rr][1] = 0.f; }
        const float* hb = bufB + warp * H * 8;
#pragma unroll
        for (int it = 0; it < H / 32; it++) {
            const int k = lane + it * 32;
            const float2 wv = ((const float2*)Wo)[k];
            const float4* hp = (const float4*)(hb + k * 8);
            const float4 h0 = hp[0], h1 = hp[1];
            r[0][0] = fmaf(h0.x, wv.x, r[0][0]); r[0][1] = fmaf(h0.x, wv.y, r[0][1]);
            r[1][0] = fmaf(h0.y, wv.x, r[1][0]); r[1][1] = fmaf(h0.y, wv.y, r[1][1]);
            r[2][0] = fmaf(h0.z, wv.x, r[2][0]); r[2][1] = fmaf(h0.z, wv.y, r[2][1]);
            r[3][0] = fmaf(h0.w, wv.x, r[3][0]); r[3][1] = fmaf(h0.w, wv.y, r[3][1]);
            r[4][0] = fmaf(h1.x, wv.x, r[4][0]); r[4][1] = fmaf(h1.x, wv.y, r[4][1]);
            r[5][0] = fmaf(h1.y, wv.x, r[5][0]); r[5][1] = fmaf(h1.y, wv.y, r[5][1]);
            r[6][0] = fmaf(h1.z, wv.x, r[6][0]); r[6][1] = fmaf(h1.z, wv.y, r[6][1]);
            r[7][0] = fmaf(h1.w, wv.x, r[7][0]); r[7][1] = fmaf(h1.w, wv.y, r[7][1]);
        }
#pragma unroll
        for (int rr = 0; rr < 8; rr++) {
#pragma unroll
            for (int off = 16; off > 0; off >>= 1) {
                r[rr][0] += __shfl_xor_sync(0xffffffffu, r[rr][0], off);
                r[rr][1] += __shfl_xor_sync(0xffffffffu, r[rr][1], off);
            }
        }
        if (lane == 0) {
            const int gs = s0 + warp;
            const float c   = r[0][0] + bo[0];
            const float Fi  = r[0][1] + bo[1];
            const float cg0 = r[1][0], cg1 = r[2][0], cg2 = r[3][0];
            const float fg0 = r[1][1], fg1 = r[2][1], fg2 = r[3][1];
            const float c_t = r[4][0];                       // d/dx3 of c
            const float trHc = r[5][0] + r[6][0] + r[7][0];  // sum d2c/dxi2
            const float fila = r[5][1] + r[6][1] + r[7][1];  // Fi laplacian
            const float jdiv = -trHc
                               - (cg0 * fg0 + cg1 * fg1 + cg2 * fg2 + c * fila)
                               + 0.1f * (cg0 + cg1 + cg2);
            const int B = BATCH;
            out[gs]              = c;
            out[B + gs]          = c_t;
            out[2 * B + gs * 3 + 0] = cg0;
            out[2 * B + gs * 3 + 1] = cg1;
            out[2 * B + gs * 3 + 2] = cg2;
            out[5 * B + gs]      = Fi;
            out[6 * B + gs * 3 + 0] = fg0;
            out[6 * B + gs * 3 + 1] = fg1;
            out[6 * B + gs * 3 + 2] = fg2;
            out[9 * B + gs]      = fila;
            out[10 * B + gs]     = jdiv;
        }
    }
}

extern "C" void kernel_launch(void* const* d_in, const int* in_sizes, int n_in,
                              void* d_out, int out_size) {
    const float* x  = (const float*)d_in[0];
    const float* W0 = (const float*)d_in[1];
    const float* b0 = (const float*)d_in[2];
    const float* W1 = (const float*)d_in[3];
    const float* b1 = (const float*)d_in[4];
    const float* W2 = (const float*)d_in[5];
    const float* b2 = (const float*)d_in[6];
    const float* W3 = (const float*)d_in[7];
    const float* b3 = (const float*)d_in[8];
    const float* Wo = (const float*)d_in[9];
    const float* bo = (const float*)d_in[10];

    cudaFuncSetAttribute(grad_mlp_kernel,
                         cudaFuncAttributeMaxDynamicSharedMemorySize, SMEM_BYTES);
    grad_mlp_kernel<<<NBLK, THREADS, SMEM_BYTES>>>(
        x, W0, b0, W1, b1, W2, b2, W3, b3, Wo, bo, (float*)d_out);
}

// round 9
// speedup vs baseline: 1.5103x; 1.1756x over previous
#include <cuda_runtime.h>

#define BATCH  16384
#define H      256
#define S      4          // samples per CTA
#define NPT    4          // neurons per thread
#define THREADS 256
#define NBLK   (BATCH / S)
// two ping-pong activation buffers: [S][H][8] floats each  (2*4*256*8*4 = 64 KB)
#define SMEM_BYTES (2 * S * H * 8 * 4)

// ---------- packed f32x2 helpers (Blackwell FFMA2 path) ----------
__device__ __forceinline__ unsigned long long pack2(float lo, float hi) {
    unsigned long long r;
    asm("mov.b64 %0, {%1, %2};" : "=l"(r) : "f"(lo), "f"(hi));
    return r;
}
__device__ __forceinline__ void unpack2(unsigned long long v, float& lo, float& hi) {
    asm("mov.b64 {%0, %1}, %2;" : "=f"(lo), "=f"(hi) : "l"(v));
}
__device__ __forceinline__ unsigned long long ffma2(unsigned long long a,
                                                    unsigned long long b,
                                                    unsigned long long c) {
    unsigned long long d;
    asm("fma.rn.f32x2 %0, %1, %2, %3;" : "=l"(d) : "l"(a), "l"(b), "l"(c));
    return d;
}

// One hidden layer. Thread computes NPT neurons (j0 + 64n) for ONE sample smp.
// All lanes of a warp share smp -> activation LDS broadcast.
// sin/sout: [S][H][8] float in shared.
__device__ __forceinline__ void hidden_layer(const float* __restrict__ W,
                                             const float* __restrict__ b,
                                             const float* sin, float* sout,
                                             int j0, int smp) {
    unsigned long long acc[NPT][4];
#pragma unroll
    for (int n = 0; n < NPT; n++) {
        acc[n][0] = pack2(b[j0 + 64 * n], 0.f);   // bias into stream 0
        acc[n][1] = 0ULL;
        acc[n][2] = 0ULL;
        acc[n][3] = 0ULL;
    }

    const float* srow = sin + smp * H * 8;

#pragma unroll 4
    for (int k0 = 0; k0 < H; k0 += 4) {
        unsigned long long wp[4][NPT];
#pragma unroll
        for (int kk = 0; kk < 4; kk++) {
#pragma unroll
            for (int n = 0; n < NPT; n++) {
                const float w = W[(k0 + kk) * H + j0 + 64 * n];
                wp[kk][n] = pack2(w, w);
            }
        }
        const ulonglong2* hp = (const ulonglong2*)(srow + k0 * 8);
        const ulonglong2 q0 = hp[0], q1 = hp[1];   // k0+0: streams 0-3, 4-7
        const ulonglong2 q2 = hp[2], q3 = hp[3];   // k0+1
        const ulonglong2 q4 = hp[4], q5 = hp[5];   // k0+2
        const ulonglong2 q6 = hp[6], q7 = hp[7];   // k0+3
#pragma unroll
        for (int n = 0; n < NPT; n++) {
            acc[n][0] = ffma2(q0.x, wp[0][n], acc[n][0]);
            acc[n][1] = ffma2(q0.y, wp[0][n], acc[n][1]);
            acc[n][2] = ffma2(q1.x, wp[0][n], acc[n][2]);
            acc[n][3] = ffma2(q1.y, wp[0][n], acc[n][3]);
            acc[n][0] = ffma2(q2.x, wp[1][n], acc[n][0]);
            acc[n][1] = ffma2(q2.y, wp[1][n], acc[n][1]);
            acc[n][2] = ffma2(q3.x, wp[1][n], acc[n][2]);
            acc[n][3] = ffma2(q3.y, wp[1][n], acc[n][3]);
            acc[n][0] = ffma2(q4.x, wp[2][n], acc[n][0]);
            acc[n][1] = ffma2(q4.y, wp[2][n], acc[n][1]);
            acc[n][2] = ffma2(q5.x, wp[2][n], acc[n][2]);
            acc[n][3] = ffma2(q5.y, wp[2][n], acc[n][3]);
            acc[n][0] = ffma2(q6.x, wp[3][n], acc[n][0]);
            acc[n][1] = ffma2(q6.y, wp[3][n], acc[n][1]);
            acc[n][2] = ffma2(q7.x, wp[3][n], acc[n][2]);
            acc[n][3] = ffma2(q7.y, wp[3][n], acc[n][3]);
        }
    }

    // coupled tanh epilogue: v, v'_i = t a'_i, v''_i = t(a''_i - 2 v a'_i^2)
#pragma unroll
    for (int n = 0; n < NPT; n++) {
        float a0, a1, a2, a3, a4, a5, a6, a7;
        unpack2(acc[n][0], a0, a1);
        unpack2(acc[n][1], a2, a3);
        unpack2(acc[n][2], a4, a5);
        unpack2(acc[n][3], a6, a7);
        const float v = tanhf(a0);
        const float t = fmaf(-v, v, 1.f);
        const float o1 = t * a1, o2 = t * a2, o3 = t * a3, o4 = t * a4;
        const float m = -2.f * v * t;
        const float o5 = fmaf(t, a5, m * a1 * a1);
        const float o6 = fmaf(t, a6, m * a2 * a2);
        const float o7 = fmaf(t, a7, m * a3 * a3);
        float4* op = (float4*)(sout + (smp * H + j0 + 64 * n) * 8);
        op[0] = make_float4(v, o1, o2, o3);
        op[1] = make_float4(o4, o5, o6, o7);
    }
}

extern "C" __global__ void __launch_bounds__(THREADS, 2)
grad_mlp_kernel(const float* __restrict__ x,
                const float* __restrict__ W0, const float* __restrict__ b0,
                const float* __restrict__ W1, const float* __restrict__ b1,
                const float* __restrict__ W2, const float* __restrict__ b2,
                const float* __restrict__ W3, const float* __restrict__ b3,
                const float* __restrict__ Wo, const float* __restrict__ bo,
                float* __restrict__ out) {
    extern __shared__ float sh[];
    float* bufA = sh;
    float* bufB = sh + S * H * 8;
    __shared__ float xsh[S * 4];

    const int tid  = threadIdx.x;
    const int warp = tid >> 5, lane = tid & 31;
    const int smp  = warp >> 1;                  // 0..3: sample handled by this warp-pair
    const int jt   = ((warp & 1) << 5) | lane;   // 0..63: base neuron
    const int s0   = blockIdx.x * S;

    if (tid < S * 4) xsh[tid] = x[s0 * 4 + tid];
    __syncthreads();

    // ---- layer 0 (4 -> 256): tangents are W0 rows, second-order pre-act = 0
#pragma unroll
    for (int n = 0; n < NPT; n++) {
        const int j = jt + 64 * n;
        const float w0 = W0[0 * H + j], w1 = W0[1 * H + j];
        const float w2 = W0[2 * H + j], w3 = W0[3 * H + j];
        float a = b0[j];
        a = fmaf(xsh[smp * 4 + 0], w0, a);
        a = fmaf(xsh[smp * 4 + 1], w1, a);
        a = fmaf(xsh[smp * 4 + 2], w2, a);
        a = fmaf(xsh[smp * 4 + 3], w3, a);
        const float v = tanhf(a);
        const float t = fmaf(-v, v, 1.f);
        const float m = -2.f * v * t;
        float4* op = (float4*)(bufA + (smp * H + j) * 8);
        op[0] = make_float4(v, t * w0, t * w1, t * w2);
        op[1] = make_float4(t * w3, m * w0 * w0, m * w1 * w1, m * w2 * w2);
    }
    __syncthreads();

    hidden_layer(W1, b1, bufA, bufB, jt, smp);
    __syncthreads();
    hidden_layer(W2, b2, bufB, bufA, jt, smp);
    __syncthreads();
    hidden_layer(W3, b3, bufA, bufB, jt, smp);
    __syncthreads();

    // ---- output layer (256 -> 2) + derived quantities: warp w handles sample w
    if (warp < S) {
        float r[8][2];
#pragma unroll
        for (int rr = 0; rr < 8; rr++) { r[rr][0] = 0.f; r[rr][1] = 0.f; }
        const float* hb = bufB + warp * H * 8;
#pragma unroll
        for (int it = 0; it < H / 32; it++) {
            const int k = lane + it * 32;
            const float2 wv = ((const float2*)Wo)[k];
            const float4* hp = (const float4*)(hb + k * 8);
            const float4 h0 = hp[0], h1 = hp[1];
            r[0][0] = fmaf(h0.x, wv.x, r[0][0]); r[0][1] = fmaf(h0.x, wv.y, r[0][1]);
            r[1][0] = fmaf(h0.y, wv.x, r[1][0]); r[1][1] = fmaf(h0.y, wv.y, r[1][1]);
            r[2][0] = fmaf(h0.z, wv.x, r[2][0]); r[2][1] = fmaf(h0.z, wv.y, r[2][1]);
            r[3][0] = fmaf(h0.w, wv.x, r[3][0]); r[3][1] = fmaf(h0.w, wv.y, r[3][1]);
            r[4][0] = fmaf(h1.x, wv.x, r[4][0]); r[4][1] = fmaf(h1.x, wv.y, r[4][1]);
            r[5][0] = fmaf(h1.y, wv.x, r[5][0]); r[5][1] = fmaf(h1.y, wv.y, r[5][1]);
            r[6][0] = fmaf(h1.z, wv.x, r[6][0]); r[6][1] = fmaf(h1.z, wv.y, r[6][1]);
            r[7][0] = fmaf(h1.w, wv.x, r[7][0]); r[7][1] = fmaf(h1.w, wv.y, r[7][1]);
        }
#pragma unroll
        for (int rr = 0; rr < 8; rr++) {
#pragma unroll
            for (int off = 16; off > 0; off >>= 1) {
                r[rr][0] += __shfl_xor_sync(0xffffffffu, r[rr][0], off);
                r[rr][1] += __shfl_xor_sync(0xffffffffu, r[rr][1], off);
            }
        }
        if (lane == 0) {
            const int gs = s0 + warp;
            const float c   = r[0][0] + bo[0];
            const float Fi  = r[0][1] + bo[1];
            const float cg0 = r[1][0], cg1 = r[2][0], cg2 = r[3][0];
            const float fg0 = r[1][1], fg1 = r[2][1], fg2 = r[3][1];
            const float c_t = r[4][0];                       // d/dx3 of c
            const float trHc = r[5][0] + r[6][0] + r[7][0];  // sum d2c/dxi2
            const float fila = r[5][1] + r[6][1] + r[7][1];  // Fi laplacian
            const float jdiv = -trHc
                               - (cg0 * fg0 + cg1 * fg1 + cg2 * fg2 + c * fila)
                               + 0.1f * (cg0 + cg1 + cg2);
            const int B = BATCH;
            out[gs]              = c;
            out[B + gs]          = c_t;
            out[2 * B + gs * 3 + 0] = cg0;
            out[2 * B + gs * 3 + 1] = cg1;
            out[2 * B + gs * 3 + 2] = cg2;
            out[5 * B + gs]      = Fi;
            out[6 * B + gs * 3 + 0] = fg0;
            out[6 * B + gs * 3 + 1] = fg1;
            out[6 * B + gs * 3 + 2] = fg2;
            out[9 * B + gs]      = fila;
            out[10 * B + gs]     = jdiv;
        }
    }
}

extern "C" void kernel_launch(void* const* d_in, const int* in_sizes, int n_in,
                              void* d_out, int out_size) {
    const float* x  = (const float*)d_in[0];
    const float* W0 = (const float*)d_in[1];
    const float* b0 = (const float*)d_in[2];
    const float* W1 = (const float*)d_in[3];
    const float* b1 = (const float*)d_in[4];
    const float* W2 = (const float*)d_in[5];
    const float* b2 = (const float*)d_in[6];
    const float* W3 = (const float*)d_in[7];
    const float* b3 = (const float*)d_in[8];
    const float* Wo = (const float*)d_in[9];
    const float* bo = (const float*)d_in[10];

    cudaFuncSetAttribute(grad_mlp_kernel,
                         cudaFuncAttributeMaxDynamicSharedMemorySize, SMEM_BYTES);
    grad_mlp_kernel<<<NBLK, THREADS, SMEM_BYTES>>>(
        x, W0, b0, W1, b1, W2, b2, W3, b3, Wo, bo, (float*)d_out);
}

// round 12
// speedup vs baseline: 1.6180x; 1.0713x over previous
#include <cuda_runtime.h>

#define BATCH  16384
#define H      256
#define S      4          // samples per CTA
#define SPT    2          // samples per thread (warp-pair owns SPT samples)
#define NPT    4          // neurons per thread
#define THREADS 128
#define NBLK   (BATCH / S)
// two ping-pong activation buffers: [S][H][8] floats each (2*4*256*8*4 = 64 KB)
#define SMEM_BYTES (2 * S * H * 8 * 4)

// ---------- packed f32x2 helpers (Blackwell FFMA2 path) ----------
__device__ __forceinline__ unsigned long long pack2(float lo, float hi) {
    unsigned long long r;
    asm("mov.b64 %0, {%1, %2};" : "=l"(r) : "f"(lo), "f"(hi));
    return r;
}
__device__ __forceinline__ void unpack2(unsigned long long v, float& lo, float& hi) {
    asm("mov.b64 {%0, %1}, %2;" : "=f"(lo), "=f"(hi) : "l"(v));
}
__device__ __forceinline__ unsigned long long ffma2(unsigned long long a,
                                                    unsigned long long b,
                                                    unsigned long long c) {
    unsigned long long d;
    asm("fma.rn.f32x2 %0, %1, %2, %3;" : "=l"(d) : "l"(a), "l"(b), "l"(c));
    return d;
}

// One hidden layer. Thread computes NPT neurons (j0 + 64n) for SPT samples
// (sbase + s). All lanes of a warp share sbase -> activation LDS broadcast.
// Weights are loaded once per chunk and reused across both samples.
// sin/sout: [S][H][8] float in shared.
__device__ __forceinline__ void hidden_layer(const float* __restrict__ W,
                                             const float* __restrict__ b,
                                             const float* sin, float* sout,
                                             int j0, int sbase) {
    unsigned long long acc[NPT][SPT][4];
#pragma unroll
    for (int n = 0; n < NPT; n++) {
        const float bj = b[j0 + 64 * n];
#pragma unroll
        for (int s = 0; s < SPT; s++) {
            acc[n][s][0] = pack2(bj, 0.f);   // bias into stream 0
            acc[n][s][1] = 0ULL;
            acc[n][s][2] = 0ULL;
            acc[n][s][3] = 0ULL;
        }
    }

#pragma unroll 2
    for (int k0 = 0; k0 < H; k0 += 4) {
        unsigned long long wp[4][NPT];
#pragma unroll
        for (int kk = 0; kk < 4; kk++) {
#pragma unroll
            for (int n = 0; n < NPT; n++) {
                const float w = W[(k0 + kk) * H + j0 + 64 * n];
                wp[kk][n] = pack2(w, w);
            }
        }
#pragma unroll
        for (int s = 0; s < SPT; s++) {
            const ulonglong2* hp =
                (const ulonglong2*)(sin + ((sbase + s) * H + k0) * 8);
            const ulonglong2 q0 = hp[0], q1 = hp[1];   // k0+0: streams 0-3,4-7
            const ulonglong2 q2 = hp[2], q3 = hp[3];   // k0+1
            const ulonglong2 q4 = hp[4], q5 = hp[5];   // k0+2
            const ulonglong2 q6 = hp[6], q7 = hp[7];   // k0+3
#pragma unroll
            for (int n = 0; n < NPT; n++) {
                acc[n][s][0] = ffma2(q0.x, wp[0][n], acc[n][s][0]);
                acc[n][s][1] = ffma2(q0.y, wp[0][n], acc[n][s][1]);
                acc[n][s][2] = ffma2(q1.x, wp[0][n], acc[n][s][2]);
                acc[n][s][3] = ffma2(q1.y, wp[0][n], acc[n][s][3]);
                acc[n][s][0] = ffma2(q2.x, wp[1][n], acc[n][s][0]);
                acc[n][s][1] = ffma2(q2.y, wp[1][n], acc[n][s][1]);
                acc[n][s][2] = ffma2(q3.x, wp[1][n], acc[n][s][2]);
                acc[n][s][3] = ffma2(q3.y, wp[1][n], acc[n][s][3]);
                acc[n][s][0] = ffma2(q4.x, wp[2][n], acc[n][s][0]);
                acc[n][s][1] = ffma2(q4.y, wp[2][n], acc[n][s][1]);
                acc[n][s][2] = ffma2(q5.x, wp[2][n], acc[n][s][2]);
                acc[n][s][3] = ffma2(q5.y, wp[2][n], acc[n][s][3]);
                acc[n][s][0] = ffma2(q6.x, wp[3][n], acc[n][s][0]);
                acc[n][s][1] = ffma2(q6.y, wp[3][n], acc[n][s][1]);
                acc[n][s][2] = ffma2(q7.x, wp[3][n], acc[n][s][2]);
                acc[n][s][3] = ffma2(q7.y, wp[3][n], acc[n][s][3]);
            }
        }
    }

    // coupled tanh epilogue: v, v'_i = t a'_i, v''_i = t(a''_i - 2 v a'_i^2)
#pragma unroll
    for (int n = 0; n < NPT; n++) {
#pragma unroll
        for (int s = 0; s < SPT; s++) {
            float a0, a1, a2, a3, a4, a5, a6, a7;
            unpack2(acc[n][s][0], a0, a1);
            unpack2(acc[n][s][1], a2, a3);
            unpack2(acc[n][s][2], a4, a5);
            unpack2(acc[n][s][3], a6, a7);
            const float v = tanhf(a0);
            const float t = fmaf(-v, v, 1.f);
            const float o1 = t * a1, o2 = t * a2, o3 = t * a3, o4 = t * a4;
            const float m = -2.f * v * t;
            const float o5 = fmaf(t, a5, m * a1 * a1);
            const float o6 = fmaf(t, a6, m * a2 * a2);
            const float o7 = fmaf(t, a7, m * a3 * a3);
            float4* op =
                (float4*)(sout + ((sbase + s) * H + j0 + 64 * n) * 8);
            op[0] = make_float4(v, o1, o2, o3);
            op[1] = make_float4(o4, o5, o6, o7);
        }
    }
}

extern "C" __global__ void __launch_bounds__(THREADS, 3)
grad_mlp_kernel(const float* __restrict__ x,
                const float* __restrict__ W0, const float* __restrict__ b0,
                const float* __restrict__ W1, const float* __restrict__ b1,
                const float* __restrict__ W2, const float* __restrict__ b2,
                const float* __restrict__ W3, const float* __restrict__ b3,
                const float* __restrict__ Wo, const float* __restrict__ bo,
                float* __restrict__ out) {
    extern __shared__ float sh[];
    float* bufA = sh;
    float* bufB = sh + S * H * 8;
    __shared__ float xsh[S * 4];

    const int tid  = threadIdx.x;
    const int warp = tid >> 5, lane = tid & 31;
    const int group = warp >> 1;                 // 0..1: sample group
    const int jt    = ((warp & 1) << 5) | lane;  // 0..63: base neuron
    const int sbase = group * SPT;
    const int s0    = blockIdx.x * S;

    if (tid < S * 4) xsh[tid] = x[s0 * 4 + tid];
    __syncthreads();

    // ---- layer 0 (4 -> 256): tangents are W0 rows, second-order pre-act = 0
#pragma unroll
    for (int n = 0; n < NPT; n++) {
        const int j = jt + 64 * n;
        const float w0 = W0[0 * H + j], w1 = W0[1 * H + j];
        const float w2 = W0[2 * H + j], w3 = W0[3 * H + j];
        const float bj = b0[j];
#pragma unroll
        for (int s = 0; s < SPT; s++) {
            const int gs = sbase + s;
            float a = bj;
            a = fmaf(xsh[gs * 4 + 0], w0, a);
            a = fmaf(xsh[gs * 4 + 1], w1, a);
            a = fmaf(xsh[gs * 4 + 2], w2, a);
            a = fmaf(xsh[gs * 4 + 3], w3, a);
            const float v = tanhf(a);
            const float t = fmaf(-v, v, 1.f);
            const float m = -2.f * v * t;
            float4* op = (float4*)(bufA + (gs * H + j) * 8);
            op[0] = make_float4(v, t * w0, t * w1, t * w2);
            op[1] = make_float4(t * w3, m * w0 * w0, m * w1 * w1, m * w2 * w2);
        }
    }
    __syncthreads();

    hidden_layer(W1, b1, bufA, bufB, jt, sbase);
    __syncthreads();
    hidden_layer(W2, b2, bufB, bufA, jt, sbase);
    __syncthreads();
    hidden_layer(W3, b3, bufA, bufB, jt, sbase);
    __syncthreads();

    // ---- output layer (256 -> 2) + derived quantities: warp w handles sample w
    if (warp < S) {
        float r[8][2];
#pragma unroll
        for (int rr = 0; rr < 8; rr++) { r[rr][0] = 0.f; r[rr][1] = 0.f; }
        const float* hb = bufB + warp * H * 8;
#pragma unroll
        for (int it = 0; it < H / 32; it++) {
            const int k = lane + it * 32;
            const float2 wv = ((const float2*)Wo)[k];
            const float4* hp = (const float4*)(hb + k * 8);
            const float4 h0 = hp[0], h1 = hp[1];
            r[0][0] = fmaf(h0.x, wv.x, r[0][0]); r[0][1] = fmaf(h0.x, wv.y, r[0][1]);
            r[1][0] = fmaf(h0.y, wv.x, r[1][0]); r[1][1] = fmaf(h0.y, wv.y, r[1][1]);
            r[2][0] = fmaf(h0.z, wv.x, r[2][0]); r[2][1] = fmaf(h0.z, wv.y, r[2][1]);
            r[3][0] = fmaf(h0.w, wv.x, r[3][0]); r[3][1] = fmaf(h0.w, wv.y, r[3][1]);
            r[4][0] = fmaf(h1.x, wv.x, r[4][0]); r[4][1] = fmaf(h1.x, wv.y, r[4][1]);
            r[5][0] = fmaf(h1.y, wv.x, r[5][0]); r[5][1] = fmaf(h1.y, wv.y, r[5][1]);
            r[6][0] = fmaf(h1.z, wv.x, r[6][0]); r[6][1] = fmaf(h1.z, wv.y, r[6][1]);
            r[7][0] = fmaf(h1.w, wv.x, r[7][0]); r[7][1] = fmaf(h1.w, wv.y, r[7][1]);
        }
#pragma unroll
        for (int rr = 0; rr < 8; rr++) {
#pragma unroll
            for (int off = 16; off > 0; off >>= 1) {
                r[rr][0] += __shfl_xor_sync(0xffffffffu, r[rr][0], off);
                r[rr][1] += __shfl_xor_sync(0xffffffffu, r[rr][1], off);
            }
        }
        if (lane == 0) {
            const int gs = s0 + warp;
            const float c   = r[0][0] + bo[0];
            const float Fi  = r[0][1] + bo[1];
            const float cg0 = r[1][0], cg1 = r[2][0], cg2 = r[3][0];
            const float fg0 = r[1][1], fg1 = r[2][1], fg2 = r[3][1];
            const float c_t = r[4][0];                       // d/dx3 of c
            const float trHc = r[5][0] + r[6][0] + r[7][0];  // sum d2c/dxi2
            const float fila = r[5][1] + r[6][1] + r[7][1];  // Fi laplacian
            const float jdiv = -trHc
                               - (cg0 * fg0 + cg1 * fg1 + cg2 * fg2 + c * fila)
                               + 0.1f * (cg0 + cg1 + cg2);
            const int B = BATCH;
            out[gs]              = c;
            out[B + gs]          = c_t;
            out[2 * B + gs * 3 + 0] = cg0;
            out[2 * B + gs * 3 + 1] = cg1;
            out[2 * B + gs * 3 + 2] = cg2;
            out[5 * B + gs]      = Fi;
            out[6 * B + gs * 3 + 0] = fg0;
            out[6 * B + gs * 3 + 1] = fg1;
            out[6 * B + gs * 3 + 2] = fg2;
            out[9 * B + gs]      = fila;
            out[10 * B + gs]     = jdiv;
        }
    }
}

extern "C" void kernel_launch(void* const* d_in, const int* in_sizes, int n_in,
                              void* d_out, int out_size) {
    const float* x  = (const float*)d_in[0];
    const float* W0 = (const float*)d_in[1];
    const float* b0 = (const float*)d_in[2];
    const float* W1 = (const float*)d_in[3];
    const float* b1 = (const float*)d_in[4];
    const float* W2 = (const float*)d_in[5];
    const float* b2 = (const float*)d_in[6];
    const float* W3 = (const float*)d_in[7];
    const float* b3 = (const float*)d_in[8];
    const float* Wo = (const float*)d_in[9];
    const float* bo = (const float*)d_in[10];

    cudaFuncSetAttribute(grad_mlp_kernel,
                         cudaFuncAttributeMaxDynamicSharedMemorySize, SMEM_BYTES);
    grad_mlp_kernel<<<NBLK, THREADS, SMEM_BYTES>>>(
        x, W0, b0, W1, b1, W2, b2, W3, b3, Wo, bo, (float*)d_out);
}